// round 14
// baseline (speedup 1.0000x reference)
#include <cuda_runtime.h>

#define DIM      1024
#define NF4      256               // float4 per row
#define N_CLS    10
#define IMG      784
#define IMGF4    196
#define N_SAMP   16384
#define ROWS     2
#define WARPS_B  24
#define TPB      (WARPS_B * 32)    // 768, one block per SM
#define GRID     152
#define TOTW     (GRID * WARPS_B)  // 3648 warps
#define NPAIRS   (N_SAMP / ROWS)   // 8192 row-pairs
#define BASE_P   (NPAIRS / TOTW)   // 2
#define REM_P    (NPAIRS - BASE_P * TOTW)   // 896 warps take 3
#define JIT      8                 // chunks per pair (128 d each)
#define DEPTH    3                 // per-warp cp.async slots
#define REF_F4   (N_CLS * NF4)     // 2560 f4 = 40KB
#define WSTG_F4  128               // slot: {re,im}x{2 rows}x32 f4 = 2KB
#define STG_F4   (WARPS_B * DEPTH * WSTG_F4)   // 9216 f4 = 144KB
#define SMEM_BYTES ((REF_F4 + STG_F4) * 16 + 256 * 4)   // ~185KB

typedef unsigned long long u64;

// ---- packed fp32x2 helpers (d-parity accumulators, proven since R3) -------
__device__ __forceinline__ void ffma2(u64& d, u64 a, u64 b) {
    asm("fma.rn.f32x2 %0, %1, %2, %0;" : "+l"(d) : "l"(a), "l"(b));
}
__device__ __forceinline__ u64 addf2(u64 a, u64 b) {
    asm("add.rn.f32x2 %0, %1, %2;" : "+l"(a) : "l"(a), "l"(b));
    return a;
}
__device__ __forceinline__ float pair_sum(u64 v) {
    return __uint_as_float((unsigned)(v & 0xffffffffu)) +
           __uint_as_float((unsigned)(v >> 32));
}

// ---- cp.async helpers ------------------------------------------------------
__device__ __forceinline__ void cp_async16(void* smem_dst, const void* gsrc) {
    unsigned saddr = (unsigned)__cvta_generic_to_shared(smem_dst);
    asm volatile("cp.async.cg.shared.global [%0], [%1], 16;"
                 :: "r"(saddr), "l"(gsrc));
}
__device__ __forceinline__ void cp_commit() {
    asm volatile("cp.async.commit_group;");
}
template <int N>
__device__ __forceinline__ void cp_wait() {
    asm volatile("cp.async.wait_group %0;" :: "n"(N));
}

// ---------------------------------------------------------------------------
// out[n][c] = (z_re[n]·ref[c])^2 + (z_im[n]·ref[c])^2
// ONE persistent 768-thread block per SM (24 warps): ref stored once in smem,
// every warp runs a private DEPTH-3 cp.async ring over its row-pairs.
// No block barriers in the main loop. d-parity packed FFMA2 compute (R5).
// ---------------------------------------------------------------------------
__global__ void __launch_bounds__(TPB, 1)
swap_test_kernel(const float* __restrict__ z_re,
                 const float* __restrict__ z_im,
                 const float* __restrict__ canon,
                 float* __restrict__ out)
{
    extern __shared__ float4 smem[];
    float4* ref_s = smem;                          // [N_CLS][NF4] 40KB
    float4* zst   = smem + REF_F4;                 // [WARPS_B][DEPTH][128]
    float*  scr   = (float*)(zst + STG_F4);        // 240 partials + 10 inv

    const int t    = threadIdx.x;
    const int warp = t >> 5;
    const int lane = t & 31;

    // balanced warp -> row-pair map: extra pairs spread across all blocks
    const int gg = warp * GRID + blockIdx.x;
    const int np = BASE_P + (gg < REM_P ? 1 : 0);
    const int nchunks = np * JIT;

    const float4* zr4 = (const float4*)z_re;
    const float4* zi4 = (const float4*)z_im;
    float4* mystg = zst + warp * (DEPTH * WSTG_F4);

    // ---- prologue: fill DEPTH slots with chunks 0..2 of pair 0 -------------
    {
        const size_t rb = (size_t)ROWS * gg * NF4;
        #pragma unroll
        for (int s = 0; s < DEPTH; ++s) {
            float4* dst = mystg + s * WSTG_F4;
            cp_async16(&dst[lane],      zr4 + rb + s * 32 + lane);
            cp_async16(&dst[32 + lane], zr4 + rb + NF4 + s * 32 + lane);
            cp_async16(&dst[64 + lane], zi4 + rb + s * 32 + lane);
            cp_async16(&dst[96 + lane], zi4 + rb + NF4 + s * 32 + lane);
            cp_commit();
        }
    }

    // ---- ref prep once per SM (hidden under prologue DRAM latency) --------
    {
        float ss[N_CLS];
        #pragma unroll
        for (int c = 0; c < N_CLS; ++c) ss[c] = 0.f;
        for (int i = t; i < IMG; i += TPB) {
            #pragma unroll
            for (int c = 0; c < N_CLS; ++c) {
                const float v = canon[c * IMG + i];
                ss[c] += v * v;
            }
        }
        #pragma unroll
        for (int c = 0; c < N_CLS; ++c)
            #pragma unroll
            for (int sh = 16; sh > 0; sh >>= 1)
                ss[c] += __shfl_xor_sync(0xffffffffu, ss[c], sh);
        if (lane == 0) {
            #pragma unroll
            for (int c = 0; c < N_CLS; ++c) scr[c * WARPS_B + warp] = ss[c];
        }
        __syncthreads();
        if (t < N_CLS) {
            float s = 0.f;
            #pragma unroll
            for (int w = 0; w < WARPS_B; ++w) s += scr[t * WARPS_B + w];
            scr[240 + t] = rsqrtf(s);
        }
        __syncthreads();
        const float4* cg4 = (const float4*)canon;   // 3136B/class: f4-aligned
        for (int idx = t; idx < REF_F4; idx += TPB) {
            const int c  = idx / NF4;
            const int d4 = idx % NF4;
            const float inv = scr[240 + c];
            float4 v = make_float4(0.f, 0.f, 0.f, 0.f);
            if (d4 < IMGF4) {
                const float4 u = cg4[c * IMGF4 + d4];
                v = make_float4(u.x * inv, u.y * inv, u.z * inv, u.w * inv);
            }
            ref_s[idx] = v;
        }
        __syncthreads();
    }

    // ---- main loop: per-warp DEPTH-3 ring, no block barriers ---------------
    int ci = 0, slot = 0;
    for (int qi = 0; qi < np; ++qi) {
        u64 accR[ROWS][N_CLS], accI[ROWS][N_CLS];
        #pragma unroll
        for (int r = 0; r < ROWS; ++r)
            #pragma unroll
            for (int c = 0; c < N_CLS; ++c) { accR[r][c] = 0ull; accI[r][c] = 0ull; }

        #pragma unroll
        for (int j = 0; j < JIT; ++j, ++ci) {
            cp_wait<DEPTH - 1>();      // with always-commit: chunk ci resident

            const float4* s = mystg + slot * WSTG_F4;
            const ulonglong2 zr0 = *(const ulonglong2*)&s[lane];
            const ulonglong2 zr1 = *(const ulonglong2*)&s[32 + lane];
            const ulonglong2 zi0 = *(const ulonglong2*)&s[64 + lane];
            const ulonglong2 zi1 = *(const ulonglong2*)&s[96 + lane];

            // refill this slot with chunk ci+DEPTH. WAR on smem safe:
            // global return latency >> the LDS reads just issued above.
            const int pf = ci + DEPTH;
            if (pf < nchunks) {
                const size_t rb = ((size_t)ROWS * (gg + (size_t)(pf >> 3) * TOTW)) * NF4
                                  + (pf & 7) * 32 + lane;
                float4* dst = mystg + slot * WSTG_F4;
                cp_async16(&dst[lane],      zr4 + rb);
                cp_async16(&dst[32 + lane], zr4 + rb + NF4);
                cp_async16(&dst[64 + lane], zi4 + rb);
                cp_async16(&dst[96 + lane], zi4 + rb + NF4);
            }
            cp_commit();               // always commit (may be empty)
            if (++slot == DEPTH) slot = 0;

            const float4* rbase = ref_s + j * 32 + lane;
            #pragma unroll
            for (int c = 0; c < N_CLS; ++c) {
                const ulonglong2 f2 = *(const ulonglong2*)&rbase[c * NF4];
                ffma2(accR[0][c], zr0.x, f2.x);
                ffma2(accR[0][c], zr0.y, f2.y);
                ffma2(accR[1][c], zr1.x, f2.x);
                ffma2(accR[1][c], zr1.y, f2.y);
                ffma2(accI[0][c], zi0.x, f2.x);
                ffma2(accI[0][c], zi0.y, f2.y);
                ffma2(accI[1][c], zi1.x, f2.x);
                ffma2(accI[1][c], zi1.y, f2.y);
            }
        }

        // ---- pair epilogue: pack (re,im), butterfly, square, write --------
        u64 pk[ROWS][N_CLS];
        #pragma unroll
        for (int r = 0; r < ROWS; ++r)
            #pragma unroll
            for (int c = 0; c < N_CLS; ++c) {
                u64 p;
                asm("mov.b64 %0, {%1, %2};" : "=l"(p)
                    : "f"(pair_sum(accR[r][c])), "f"(pair_sum(accI[r][c])));
                pk[r][c] = p;
            }
        #pragma unroll
        for (int sh = 16; sh > 0; sh >>= 1)
            #pragma unroll
            for (int r = 0; r < ROWS; ++r)
                #pragma unroll
                for (int c = 0; c < N_CLS; ++c)
                    pk[r][c] = addf2(pk[r][c],
                                     __shfl_xor_sync(0xffffffffu, pk[r][c], sh));

        const size_t rowbase = (size_t)ROWS * (gg + (size_t)qi * TOTW);
        #pragma unroll
        for (int c = 0; c < N_CLS; ++c) {
            if (lane == c) {
                #pragma unroll
                for (int r = 0; r < ROWS; ++r) {
                    const float re = __uint_as_float((unsigned)(pk[r][c] & 0xffffffffu));
                    const float im = __uint_as_float((unsigned)(pk[r][c] >> 32));
                    out[(rowbase + r) * N_CLS + c] = re * re + im * im;
                }
            }
        }
    }
}

// ---------------------------------------------------------------------------
extern "C" void kernel_launch(void* const* d_in, const int* in_sizes, int n_in,
                              void* d_out, int out_size) {
    const float* z_re  = (const float*)d_in[0];
    const float* z_im  = (const float*)d_in[1];
    const float* canon = (const float*)d_in[2];
    float* out = (float*)d_out;

    static bool attr_set = false;
    if (!attr_set) {
        cudaFuncSetAttribute(swap_test_kernel,
                             cudaFuncAttributeMaxDynamicSharedMemorySize,
                             SMEM_BYTES);
        attr_set = true;
    }

    swap_test_kernel<<<GRID, TPB, SMEM_BYTES>>>(z_re, z_im, canon, out);
}

// round 15
// speedup vs baseline: 2.1027x; 2.1027x over previous
#include <cuda_runtime.h>

#define DIM      1024
#define NF4      256               // float4 per row
#define N_CLS    10
#define IMG      784
#define IMGF4    196
#define N_SAMP   16384
#define ROWS     2
#define WARPS_B  16
#define TPB      (WARPS_B * 32)    // 512, one block per SM, 128-reg cap
#define GRID     152
#define NPAIRS   (N_SAMP / ROWS)   // 8192 row-pairs
#define JIT      8                 // chunks per pair (128 d each)
#define DEPTH    5                 // per-warp cp.async ring slots
#define PF_DIST  8                 // L2 prefetch distance in chunks
#define REF_F4   (N_CLS * NF4)     // 2560 f4 = 40KB
#define WSTG_F4  128               // slot: {re,im}x{2 rows}x32 f4 = 2KB
#define STG_F4   (WARPS_B * DEPTH * WSTG_F4)   // 10240 f4 = 160KB
#define SMEM_BYTES ((REF_F4 + STG_F4) * 16 + 256 * 4)   // ~201KB

typedef unsigned long long u64;

// ---- packed fp32x2 helpers (d-parity accumulators, proven since R4) -------
__device__ __forceinline__ void ffma2(u64& d, u64 a, u64 b) {
    asm("fma.rn.f32x2 %0, %1, %2, %0;" : "+l"(d) : "l"(a), "l"(b));
}
__device__ __forceinline__ u64 addf2(u64 a, u64 b) {
    asm("add.rn.f32x2 %0, %1, %2;" : "+l"(a) : "l"(a), "l"(b));
    return a;
}
__device__ __forceinline__ float pair_sum(u64 v) {
    return __uint_as_float((unsigned)(v & 0xffffffffu)) +
           __uint_as_float((unsigned)(v >> 32));
}

// ---- cp.async / prefetch helpers -------------------------------------------
__device__ __forceinline__ void cp_async16(void* smem_dst, const void* gsrc) {
    unsigned saddr = (unsigned)__cvta_generic_to_shared(smem_dst);
    asm volatile("cp.async.cg.shared.global [%0], [%1], 16;"
                 :: "r"(saddr), "l"(gsrc));
}
__device__ __forceinline__ void cp_commit() {
    asm volatile("cp.async.commit_group;");
}
template <int N>
__device__ __forceinline__ void cp_wait() {
    asm volatile("cp.async.wait_group %0;" :: "n"(N));
}
__device__ __forceinline__ void pf_l2(const void* g) {
    asm volatile("prefetch.global.L2 [%0];" :: "l"(g));
}

// ---------------------------------------------------------------------------
// out[n][c] = (z_re[n]·ref[c])^2 + (z_im[n]·ref[c])^2
// One 512-thread block per SM (16 warps, 128 regs — the proven body fits).
// ref stored once in smem. Each warp: private DEPTH-5 cp.async ring +
// L2 prefetch PF_DIST chunks ahead. Contiguous per-SM pair range.
// No block barriers in the main loop. d-parity packed FFMA2 compute.
// ---------------------------------------------------------------------------
__global__ void __launch_bounds__(TPB, 1)
swap_test_kernel(const float* __restrict__ z_re,
                 const float* __restrict__ z_im,
                 const float* __restrict__ canon,
                 float* __restrict__ out)
{
    extern __shared__ float4 smem[];
    float4* ref_s = smem;                          // [N_CLS][NF4] 40KB
    float4* zst   = smem + REF_F4;                 // [WARPS_B][DEPTH][128]
    float*  scr   = (float*)(zst + STG_F4);        // partials + inv norms

    const int t    = threadIdx.x;
    const int warp = t >> 5;
    const int lane = t & 31;
    const int b    = blockIdx.x;

    // contiguous pair range for this SM; warps interleave inside it
    const int p0 = (b * NPAIRS) / GRID;
    const int np = ((b + 1) * NPAIRS) / GRID - p0;        // 53 or 54
    const int nk = (np - warp + WARPS_B - 1) / WARPS_B;   // pairs for this warp
    const int nchunks = nk * JIT;

    const float4* zr4 = (const float4*)z_re;
    const float4* zi4 = (const float4*)z_im;
    float4* mystg = zst + warp * (DEPTH * WSTG_F4);

    // ---- prologue: fill DEPTH slots with chunks 0..4 of pair #0 ------------
    {
        const size_t rb = (size_t)ROWS * (p0 + warp) * NF4;
        #pragma unroll
        for (int s = 0; s < DEPTH; ++s) {
            float4* dst = mystg + s * WSTG_F4;
            cp_async16(&dst[lane],      zr4 + rb + s * 32 + lane);
            cp_async16(&dst[32 + lane], zr4 + rb + NF4 + s * 32 + lane);
            cp_async16(&dst[64 + lane], zi4 + rb + s * 32 + lane);
            cp_async16(&dst[96 + lane], zi4 + rb + NF4 + s * 32 + lane);
            cp_commit();
        }
    }

    // ---- ref prep once per SM (hidden under prologue DRAM latency) ---------
    {
        float ss[N_CLS];
        #pragma unroll
        for (int c = 0; c < N_CLS; ++c) ss[c] = 0.f;
        for (int i = t; i < IMG; i += TPB) {
            #pragma unroll
            for (int c = 0; c < N_CLS; ++c) {
                const float v = canon[c * IMG + i];
                ss[c] += v * v;
            }
        }
        #pragma unroll
        for (int c = 0; c < N_CLS; ++c)
            #pragma unroll
            for (int sh = 16; sh > 0; sh >>= 1)
                ss[c] += __shfl_xor_sync(0xffffffffu, ss[c], sh);
        if (lane == 0) {
            #pragma unroll
            for (int c = 0; c < N_CLS; ++c) scr[c * WARPS_B + warp] = ss[c];
        }
        __syncthreads();
        if (t < N_CLS) {
            float s = 0.f;
            #pragma unroll
            for (int w = 0; w < WARPS_B; ++w) s += scr[t * WARPS_B + w];
            scr[192 + t] = rsqrtf(s);
        }
        __syncthreads();
        const float4* cg4 = (const float4*)canon;   // 3136B/class: f4-aligned
        for (int idx = t; idx < REF_F4; idx += TPB) {
            const int c  = idx / NF4;
            const int d4 = idx % NF4;
            const float inv = scr[192 + c];
            float4 v = make_float4(0.f, 0.f, 0.f, 0.f);
            if (d4 < IMGF4) {
                const float4 u = cg4[c * IMGF4 + d4];
                v = make_float4(u.x * inv, u.y * inv, u.z * inv, u.w * inv);
            }
            ref_s[idx] = v;
        }
        __syncthreads();
    }

    // ---- main loop: per-warp DEPTH-5 ring + L2 prefetch, no barriers -------
    int ci = 0, slot = 0;
    for (int k = 0; k < nk; ++k) {
        const int pair = p0 + k * WARPS_B + warp;

        u64 accR[ROWS][N_CLS], accI[ROWS][N_CLS];
        #pragma unroll
        for (int r = 0; r < ROWS; ++r)
            #pragma unroll
            for (int c = 0; c < N_CLS; ++c) { accR[r][c] = 0ull; accI[r][c] = 0ull; }

        #pragma unroll
        for (int j = 0; j < JIT; ++j, ++ci) {
            // L2 prefetch chunk ci+PF_DIST (same j, next pair) — 16 lanes
            // each touch one distinct 128B line => whole 2KB chunk.
            {
                const int k2 = (ci + PF_DIST) >> 3;
                if (lane < 16 && k2 * WARPS_B + warp < np) {
                    const size_t row2 = (size_t)ROWS * (p0 + k2 * WARPS_B + warp)
                                        + ((lane >> 2) & 1);
                    const char* base = (lane & 8) ? (const char*)z_im
                                                  : (const char*)z_re;
                    pf_l2(base + row2 * (DIM * 4) + j * 512 + (lane & 3) * 128);
                }
            }

            cp_wait<DEPTH - 1>();      // with always-commit: chunk ci resident

            const float4* s = mystg + slot * WSTG_F4;
            const ulonglong2 zr0 = *(const ulonglong2*)&s[lane];
            const ulonglong2 zr1 = *(const ulonglong2*)&s[32 + lane];
            const ulonglong2 zi0 = *(const ulonglong2*)&s[64 + lane];
            const ulonglong2 zi1 = *(const ulonglong2*)&s[96 + lane];

            // refill this slot with chunk ci+DEPTH. WAR on smem safe:
            // global return latency >> the LDS reads just issued above.
            {
                const int pf = ci + DEPTH;
                const int k3 = pf >> 3;
                if (k3 * WARPS_B + warp < np) {
                    const size_t rb = (size_t)ROWS * (p0 + k3 * WARPS_B + warp) * NF4
                                      + (pf & 7) * 32 + lane;
                    float4* dst = mystg + slot * WSTG_F4;
                    cp_async16(&dst[lane],      zr4 + rb);
                    cp_async16(&dst[32 + lane], zr4 + rb + NF4);
                    cp_async16(&dst[64 + lane], zi4 + rb);
                    cp_async16(&dst[96 + lane], zi4 + rb + NF4);
                }
            }
            cp_commit();               // always commit (may be empty)
            if (++slot == DEPTH) slot = 0;

            const float4* rbase = ref_s + j * 32 + lane;
            #pragma unroll
            for (int c = 0; c < N_CLS; ++c) {
                const ulonglong2 f2 = *(const ulonglong2*)&rbase[c * NF4];
                ffma2(accR[0][c], zr0.x, f2.x);
                ffma2(accR[0][c], zr0.y, f2.y);
                ffma2(accR[1][c], zr1.x, f2.x);
                ffma2(accR[1][c], zr1.y, f2.y);
                ffma2(accI[0][c], zi0.x, f2.x);
                ffma2(accI[0][c], zi0.y, f2.y);
                ffma2(accI[1][c], zi1.x, f2.x);
                ffma2(accI[1][c], zi1.y, f2.y);
            }
        }

        // ---- pair epilogue: pack (re,im), butterfly, square, write --------
        u64 pk[ROWS][N_CLS];
        #pragma unroll
        for (int r = 0; r < ROWS; ++r)
            #pragma unroll
            for (int c = 0; c < N_CLS; ++c) {
                u64 p;
                asm("mov.b64 %0, {%1, %2};" : "=l"(p)
                    : "f"(pair_sum(accR[r][c])), "f"(pair_sum(accI[r][c])));
                pk[r][c] = p;
            }
        #pragma unroll
        for (int sh = 16; sh > 0; sh >>= 1)
            #pragma unroll
            for (int r = 0; r < ROWS; ++r)
                #pragma unroll
                for (int c = 0; c < N_CLS; ++c)
                    pk[r][c] = addf2(pk[r][c],
                                     __shfl_xor_sync(0xffffffffu, pk[r][c], sh));

        const size_t rowbase = (size_t)ROWS * pair;
        #pragma unroll
        for (int c = 0; c < N_CLS; ++c) {
            if (lane == c) {
                #pragma unroll
                for (int r = 0; r < ROWS; ++r) {
                    const float re = __uint_as_float((unsigned)(pk[r][c] & 0xffffffffu));
                    const float im = __uint_as_float((unsigned)(pk[r][c] >> 32));
                    out[(rowbase + r) * N_CLS + c] = re * re + im * im;
                }
            }
        }
    }
}

// ---------------------------------------------------------------------------
extern "C" void kernel_launch(void* const* d_in, const int* in_sizes, int n_in,
                              void* d_out, int out_size) {
    const float* z_re  = (const float*)d_in[0];
    const float* z_im  = (const float*)d_in[1];
    const float* canon = (const float*)d_in[2];
    float* out = (float*)d_out;

    static bool attr_set = false;
    if (!attr_set) {
        cudaFuncSetAttribute(swap_test_kernel,
                             cudaFuncAttributeMaxDynamicSharedMemorySize,
                             SMEM_BYTES);
        attr_set = true;
    }

    swap_test_kernel<<<GRID, TPB, SMEM_BYTES>>>(z_re, z_im, canon, out);
}